// round 13
// baseline (speedup 1.0000x reference)
#include <cuda_runtime.h>
#include <math.h>

// ---------------------------------------------------------------------------
// Shapes
// ---------------------------------------------------------------------------
#define D        32
#define NU_C     100001
#define NI_C     50001
#define NTOT_C   (NU_C + NI_C)          // 150002
#define NOFF     (NTOT_C + 1)
#define BMAX     4096
#define SCAN_B   256
#define NBLK_SCAN ((NOFF + SCAN_B - 1) / SCAN_B)
#define SUMS_STRIDE 640
#define CSR_CAP  6400000                // float4 entries

// ---------------------------------------------------------------------------
// Device scratch
// ---------------------------------------------------------------------------
__device__ float g_emb[NTOT_C * D];
__device__ float g_pc0[NTOT_C * D];     // comb0 layer1
__device__ float g_pc1[NTOT_C * D];     // comb1 layer1
__device__ float g_ae0[NTOT_C * D];     // ae0
__device__ float g_ae1[NTOT_C * D];     // ae1
__device__ float g_a0 [NTOT_C * D];     // aux0 layer1; later de0 layer1
__device__ float g_a1 [NTOT_C * D];     // aux1 layer1; later de1 layer1
__device__ int    g_degi [3 * NTOT_C];  // aux0, aux1, tgt
__device__ float  g_dnv  [5 * NTOT_C];  // SoA: c0, c1, a0, a1, t
__device__ float2 g_dnv2 [3 * NTOT_C];  // pairs: (c0,a0), (c1,a1), (c0,c1)
__device__ int   g_off  [3 * NOFF];
__device__ int   g_curs [3 * NOFF];
__device__ int   g_bsums[3 * SUMS_STRIDE];
__device__ float4 g_csr [CSR_CAP];      // {idx_bits, w1, w2, w3}
// score slots: CP=0 CN=1 AP=2 AN=3 DP=4 DN=5; offset = (slot*2 + idx)*BMAX + b
__device__ float g_sc  [12 * BMAX];
__device__ float g_scal[4];

// ---------------------------------------------------------------------------
// Helpers
// ---------------------------------------------------------------------------
__device__ __forceinline__ float logsig(float x) {
    return (x >= 0.f) ? -log1pf(expf(-x)) : (x - log1pf(expf(x)));
}

__device__ __forceinline__ float wsel(float4 e, int c) {
    return (c == 0) ? e.y : ((c == 1) ? e.z : e.w);
}

// fat-CSR weighted gather: one entry LDG + one row LDG per edge, unroll 8
__device__ __forceinline__ float gather_f(const float4* __restrict__ csr,
                                          int k, int end, int wc,
                                          const float* __restrict__ src,
                                          int lane) {
    float acc = 0.f;
    for (; k + 8 <= end; k += 8) {
        float4 e[8];
        #pragma unroll
        for (int j = 0; j < 8; j++) e[j] = __ldg(&csr[k + j]);
        #pragma unroll
        for (int j = 0; j < 8; j++) {
            int idx = __float_as_int(e[j].x);
            acc = fmaf(wsel(e[j], wc), __ldg(&src[(size_t)idx * D + lane]), acc);
        }
    }
    for (; k < end; k++) {
        float4 e = __ldg(&csr[k]);
        int idx = __float_as_int(e.x);
        acc = fmaf(wsel(e, wc), __ldg(&src[(size_t)idx * D + lane]), acc);
    }
    return acc;
}

// ---------------------------------------------------------------------------
// Graph build
// ---------------------------------------------------------------------------
__global__ void k_deg3(const int2* __restrict__ aux, const int2* __restrict__ tgt,
                       int Ea, int Et, int nu) {
    int t = blockIdx.x * blockDim.x + threadIdx.x;
    int2 ed; int slot;
    if (t < 2 * Ea)            { ed = aux[t];          slot = (t < Ea) ? 0 : 1; }
    else if (t < 2 * Ea + Et)  { ed = tgt[t - 2 * Ea]; slot = 2; }
    else return;
    int* deg = g_degi + slot * NTOT_C;
    atomicAdd(&deg[ed.x], 1);
    atomicAdd(&deg[nu + ed.y], 1);
}

__global__ void k_dinv5() {
    int i = blockIdx.x * blockDim.x + threadIdx.x;
    if (i >= NTOT_C) return;
    int d0 = g_degi[0 * NTOT_C + i];
    int d1 = g_degi[1 * NTOT_C + i];
    int dt = g_degi[2 * NTOT_C + i];
    int dd[5] = {d0 + dt, d1 + dt, d0, d1, dt};
    float w[5];
    #pragma unroll
    for (int s = 0; s < 5; s++) {
        w[s] = (dd[s] > 0) ? rsqrtf((float)dd[s]) : 0.f;
        g_dnv[s * NTOT_C + i] = w[s];
    }
    g_dnv2[0 * NTOT_C + i] = make_float2(w[0], w[2]);  // (c0, a0)
    g_dnv2[1 * NTOT_C + i] = make_float2(w[1], w[3]);  // (c1, a1)
    g_dnv2[2 * NTOT_C + i] = make_float2(w[0], w[1]);  // (c0, c1)
}

__global__ void k_scanA() {
    int g = blockIdx.y;
    const int* deg = g_degi + g * NTOT_C;
    int* out  = g_off   + g * NOFF;
    int* sums = g_bsums + g * SUMS_STRIDE;
    int idx = blockIdx.x * SCAN_B + threadIdx.x;
    int val = (idx < NTOT_C) ? deg[idx] : 0;
    int lane = threadIdx.x & 31, wid = threadIdx.x >> 5;
    int x = val;
    #pragma unroll
    for (int o = 1; o < 32; o <<= 1) {
        int y = __shfl_up_sync(0xffffffffu, x, o);
        if (lane >= o) x += y;
    }
    __shared__ int ws[8], wbase[8];
    if (lane == 31) ws[wid] = x;
    __syncthreads();
    if (threadIdx.x == 0) {
        int s = 0;
        for (int i = 0; i < 8; i++) { wbase[i] = s; s += ws[i]; }
    }
    __syncthreads();
    int incl = x + wbase[wid];
    if (idx < NOFF) out[idx] = incl - val;
    if (threadIdx.x == SCAN_B - 1) sums[blockIdx.x] = incl;
}

__global__ void k_scanB(int nb) {
    int g = blockIdx.x;
    int* sums = g_bsums + g * SUMS_STRIDE;
    __shared__ int sh[SUMS_STRIDE];
    int tid = threadIdx.x;
    int orig = 0;
    if (tid < nb) { orig = sums[tid]; sh[tid] = orig; }
    __syncthreads();
    for (int o = 1; o < nb; o <<= 1) {
        int v = 0;
        if (tid < nb && tid >= o) v = sh[tid - o];
        __syncthreads();
        if (tid < nb && tid >= o) sh[tid] += v;
        __syncthreads();
    }
    if (tid < nb) sums[tid] = sh[tid] - orig;
}

__global__ void k_scanC() {
    int g = blockIdx.y;
    int idx = blockIdx.x * SCAN_B + threadIdx.x;
    if (idx < NOFF)
        g_off[g * NOFF + idx] += g_bsums[g * SUMS_STRIDE + blockIdx.x];
}

// fat fill: entry carries the per-neighbor weights for all consumers
__global__ void k_fill3(const int2* __restrict__ aux, const int2* __restrict__ tgt,
                        int Ea, int Et, int nu) {
    int t = blockIdx.x * blockDim.x + threadIdx.x;
    int2 ed; int slot; long long base;
    if (t < 2 * Ea) {
        ed = aux[t];
        slot = (t < Ea) ? 0 : 1;
        base = (t < Ea) ? 0 : 2LL * Ea;
    } else if (t < 2 * Ea + Et) {
        ed = tgt[t - 2 * Ea]; slot = 2; base = 4LL * Ea;
    } else return;
    int u = ed.x, v = nu + ed.y;
    float4 eu, ev;
    if (slot < 2) {
        float2 pv = g_dnv2[slot * NTOT_C + v];   // (comb, aux) of v
        float2 pu = g_dnv2[slot * NTOT_C + u];
        ev = make_float4(__int_as_float(v), pv.x, pv.y, 0.f);
        eu = make_float4(__int_as_float(u), pu.x, pu.y, 0.f);
    } else {
        float2 pv = g_dnv2[2 * NTOT_C + v];      // (c0, c1) of v
        float2 pu = g_dnv2[2 * NTOT_C + u];
        float tv = g_dnv[4 * NTOT_C + v];
        float tu = g_dnv[4 * NTOT_C + u];
        ev = make_float4(__int_as_float(v), pv.x, pv.y, tv);
        eu = make_float4(__int_as_float(u), pu.x, pu.y, tu);
    }
    int* curs = g_curs + slot * NOFF;
    float4* csr = g_csr + base;
    csr[atomicAdd(&curs[u], 1)] = ev;
    csr[atomicAdd(&curs[v], 1)] = eu;
}

// ---------------------------------------------------------------------------
// Propagation
// ---------------------------------------------------------------------------
// Both aux layer-1 passes in one launch (grid.y = idx): w1->comb, w2->aux.
__global__ void __launch_bounds__(256)
k_l1aux(const float4* __restrict__ csrA0, const int* __restrict__ offA0,
        const float4* __restrict__ csrA1, const int* __restrict__ offA1,
        const float* __restrict__ src,
        float* __restrict__ pc0, float* __restrict__ a0,
        float* __restrict__ pc1, float* __restrict__ a1, int ntot) {
    int u = (blockIdx.x * blockDim.x + threadIdx.x) >> 5;
    if (u >= ntot) return;
    int lane = threadIdx.x & 31;
    int y = blockIdx.y;
    const float4* csr = y ? csrA1 : csrA0;
    const int* off = y ? offA1 : offA0;
    const float* wXs = g_dnv + y * NTOT_C;
    const float* wYs = g_dnv + (2 + y) * NTOT_C;
    float* oX = y ? pc1 : pc0;
    float* oY = y ? a1 : a0;
    int k = off[u], end = off[u + 1];
    float accX = 0.f, accY = 0.f;
    for (; k + 8 <= end; k += 8) {
        float4 e[8];
        #pragma unroll
        for (int j = 0; j < 8; j++) e[j] = __ldg(&csr[k + j]);
        #pragma unroll
        for (int j = 0; j < 8; j++) {
            float v = __ldg(&src[(size_t)__float_as_int(e[j].x) * D + lane]);
            accX = fmaf(e[j].y, v, accX);
            accY = fmaf(e[j].z, v, accY);
        }
    }
    for (; k < end; k++) {
        float4 e = __ldg(&csr[k]);
        float v = __ldg(&src[(size_t)__float_as_int(e.x) * D + lane]);
        accX = fmaf(e.y, v, accX);
        accY = fmaf(e.z, v, accY);
    }
    size_t o = (size_t)u * D + lane;
    oX[o] = __ldg(&wXs[u]) * accX;
    oY[o] = __ldg(&wYs[u]) * accY;
}

// tgt layer-1: w1->comb0, w2->comb1, accumulate into pc0/pc1
__global__ void __launch_bounds__(256)
k_l1tgt(const float4* __restrict__ csr, const int* __restrict__ off,
        const float* __restrict__ src,
        float* __restrict__ pc0, float* __restrict__ pc1, int ntot) {
    int u = (blockIdx.x * blockDim.x + threadIdx.x) >> 5;
    if (u >= ntot) return;
    int lane = threadIdx.x & 31;
    int k = off[u], end = off[u + 1];
    float accX = 0.f, accY = 0.f;
    for (; k + 8 <= end; k += 8) {
        float4 e[8];
        #pragma unroll
        for (int j = 0; j < 8; j++) e[j] = __ldg(&csr[k + j]);
        #pragma unroll
        for (int j = 0; j < 8; j++) {
            float v = __ldg(&src[(size_t)__float_as_int(e[j].x) * D + lane]);
            accX = fmaf(e[j].y, v, accX);
            accY = fmaf(e[j].z, v, accY);
        }
    }
    for (; k < end; k++) {
        float4 e = __ldg(&csr[k]);
        float v = __ldg(&src[(size_t)__float_as_int(e.x) * D + lane]);
        accX = fmaf(e.y, v, accX);
        accY = fmaf(e.z, v, accY);
    }
    size_t o = (size_t)u * D + lane;
    pc0[o] += __ldg(&g_dnv[u]) * accX;
    pc1[o] += __ldg(&g_dnv[NTOT_C + u]) * accY;
}

// aux layer-2 for BOTH graphs in one launch (grid.y); weight = w2 component
__global__ void __launch_bounds__(256)
k_gcn2(const float4* __restrict__ csrA0, const int* __restrict__ offA0,
       const float4* __restrict__ csrA1, const int* __restrict__ offA1,
       const float* __restrict__ a0, const float* __restrict__ a1,
       const float* __restrict__ base,
       float* __restrict__ ae0, float* __restrict__ ae1, int ntot) {
    int u = (blockIdx.x * blockDim.x + threadIdx.x) >> 5;
    if (u >= ntot) return;
    int lane = threadIdx.x & 31;
    int y = blockIdx.y;
    const float4* csr = y ? csrA1 : csrA0;
    const int* off = y ? offA1 : offA0;
    const float* w = g_dnv + (2 + y) * NTOT_C;
    const float* src = y ? a1 : a0;
    float* out = y ? ae1 : ae0;
    float acc = gather_f(csr, off[u], off[u + 1], 1, src, lane);
    size_t o = (size_t)u * D + lane;
    out[o] = (__ldg(&w[u]) * acc + src[o] + base[o]) * (1.f / 3.f);
}

// de layer1: tgt fat csr (w3), two srcs -> two outputs
__global__ void __launch_bounds__(256)
k_dual_s(const float4* __restrict__ csr, const int* __restrict__ off,
         const float* __restrict__ s0, const float* __restrict__ s1,
         const float* __restrict__ w,
         float* __restrict__ o0, float* __restrict__ o1, int ntot) {
    int u = (blockIdx.x * blockDim.x + threadIdx.x) >> 5;
    if (u >= ntot) return;
    int lane = threadIdx.x & 31;
    int k = off[u], end = off[u + 1];
    float a0 = 0.f, a1 = 0.f;
    for (; k + 8 <= end; k += 8) {
        float4 e[8];
        #pragma unroll
        for (int j = 0; j < 8; j++) e[j] = __ldg(&csr[k + j]);
        #pragma unroll
        for (int j = 0; j < 8; j++) {
            size_t ro = (size_t)__float_as_int(e[j].x) * D + lane;
            a0 = fmaf(e[j].w, __ldg(&s0[ro]), a0);
            a1 = fmaf(e[j].w, __ldg(&s1[ro]), a1);
        }
    }
    for (; k < end; k++) {
        float4 e = __ldg(&csr[k]);
        size_t ro = (size_t)__float_as_int(e.x) * D + lane;
        a0 = fmaf(e.w, __ldg(&s0[ro]), a0);
        a1 = fmaf(e.w, __ldg(&s1[ro]), a1);
    }
    size_t o = (size_t)u * D + lane;
    float wu = __ldg(&w[u]);
    o0[o] = wu * a0;
    o1[o] = wu * a1;
}

// comb scoring: sparse layer2 over (aux csr w1 + tgt csr w1/w2); grid.y = idx
__global__ void k_score_comb(const float4* __restrict__ csrA0, const int* __restrict__ offA0,
                             const float4* __restrict__ csrA1, const int* __restrict__ offA1,
                             const float4* __restrict__ csrT, const int* __restrict__ offT,
                             const float* __restrict__ w0, const float* __restrict__ w1,
                             const float* __restrict__ nxt0, const float* __restrict__ nxt1,
                             const float* __restrict__ base,
                             const int* __restrict__ batch, int B, int nu) {
    int which = blockIdx.y;
    const float4* csrA = which ? csrA1 : csrA0;
    const int* offA = which ? offA1 : offA0;
    const float* w   = which ? w1 : w0;
    const float* nxt = which ? nxt1 : nxt0;
    int wp = (blockIdx.x * blockDim.x + threadIdx.x) >> 5;
    if (wp >= B) return;
    int lane = threadIdx.x & 31;
    const int* row = batch + (size_t)wp * 9;
    int nd[3] = {row[0], nu + row[1], nu + row[2]};
    float val[3];
    #pragma unroll
    for (int t = 0; t < 3; t++) {
        int r = nd[t];
        float g = gather_f(csrA, offA[r], offA[r + 1], 0, nxt, lane)
                + gather_f(csrT, offT[r], offT[r + 1], which, nxt, lane);
        size_t o = (size_t)r * D + lane;
        val[t] = base[o] + nxt[o] + __ldg(&w[r]) * g;
    }
    float pp = val[0] * val[1], nn = val[0] * val[2];
    #pragma unroll
    for (int o = 16; o; o >>= 1) {
        pp += __shfl_xor_sync(0xffffffffu, pp, o);
        nn += __shfl_xor_sync(0xffffffffu, nn, o);
    }
    if (lane == 0) {
        g_sc[(0 * 2 + which) * BMAX + wp] = fmaxf(pp * (1.f / 9.f), 0.f);
        g_sc[(1 * 2 + which) * BMAX + wp] = fmaxf(nn * (1.f / 9.f), 0.f);
    }
}

// de scoring for both idx: sparse layer2 over tgt fat csr (w3), dual source
__global__ void k_score_de(const float4* __restrict__ csrT, const int* __restrict__ offT,
                           const float* __restrict__ wT,
                           const float* __restrict__ d0, const float* __restrict__ d1,
                           const float* __restrict__ ae0, const float* __restrict__ ae1,
                           const int* __restrict__ batch, int B, int nu) {
    int wp = (blockIdx.x * blockDim.x + threadIdx.x) >> 5;
    if (wp >= B) return;
    int lane = threadIdx.x & 31;
    const int* row = batch + (size_t)wp * 9;
    int nd[3] = {row[0], nu + row[1], nu + row[2]};
    float v0[3], v1[3];
    #pragma unroll
    for (int t = 0; t < 3; t++) {
        int r = nd[t];
        int k = offT[r], end = offT[r + 1];
        float a0 = 0.f, a1 = 0.f;
        for (; k + 8 <= end; k += 8) {
            float4 e[8];
            #pragma unroll
            for (int j = 0; j < 8; j++) e[j] = __ldg(&csrT[k + j]);
            #pragma unroll
            for (int j = 0; j < 8; j++) {
                size_t ro = (size_t)__float_as_int(e[j].x) * D + lane;
                a0 = fmaf(e[j].w, __ldg(&d0[ro]), a0);
                a1 = fmaf(e[j].w, __ldg(&d1[ro]), a1);
            }
        }
        for (; k < end; k++) {
            float4 e = __ldg(&csrT[k]);
            size_t ro = (size_t)__float_as_int(e.x) * D + lane;
            a0 = fmaf(e.w, __ldg(&d0[ro]), a0);
            a1 = fmaf(e.w, __ldg(&d1[ro]), a1);
        }
        size_t o = (size_t)r * D + lane;
        float wr = __ldg(&wT[r]);
        v0[t] = ae0[o] + d0[o] + wr * a0;
        v1[t] = ae1[o] + d1[o] + wr * a1;
    }
    float pp0 = v0[0] * v0[1], nn0 = v0[0] * v0[2];
    float pp1 = v1[0] * v1[1], nn1 = v1[0] * v1[2];
    #pragma unroll
    for (int o = 16; o; o >>= 1) {
        pp0 += __shfl_xor_sync(0xffffffffu, pp0, o);
        nn0 += __shfl_xor_sync(0xffffffffu, nn0, o);
        pp1 += __shfl_xor_sync(0xffffffffu, pp1, o);
        nn1 += __shfl_xor_sync(0xffffffffu, nn1, o);
    }
    if (lane == 0) {
        g_sc[ 8 * BMAX + wp] = fmaxf(pp0 * (1.f / 9.f), 0.f);
        g_sc[10 * BMAX + wp] = fmaxf(nn0 * (1.f / 9.f), 0.f);
        g_sc[ 9 * BMAX + wp] = fmaxf(pp1 * (1.f / 9.f), 0.f);
        g_sc[11 * BMAX + wp] = fmaxf(nn1 * (1.f / 9.f), 0.f);
    }
}

// AP/AN + aux BPR for both idx
__global__ void k_scores_aux2(const float* __restrict__ ae0, const float* __restrict__ ae1,
                              const int* __restrict__ batch, int B, int nu) {
    __shared__ float sh0[8], sh1[8];
    int warp = (blockIdx.x * blockDim.x + threadIdx.x) >> 5;
    int lane = threadIdx.x & 31;
    int wid  = threadIdx.x >> 5;
    float val0 = 0.f, val1 = 0.f;
    if (warp < B) {
        const int* row = batch + (size_t)warp * 9;
        int u = row[0], p = nu + row[1], n = nu + row[2];
        size_t ou = (size_t)u * D + lane, op = (size_t)p * D + lane, on = (size_t)n * D + lane;
        float e0u = ae0[ou], e1u = ae1[ou];
        float pp0 = e0u * ae0[op], nn0 = e0u * ae0[on];
        float pp1 = e1u * ae1[op], nn1 = e1u * ae1[on];
        const int* r0 = row + 3;
        const int* r1 = row + 6;
        float a0u = ae0[(size_t)r0[0] * D + lane];
        float ps0 = a0u * ae0[(size_t)(nu + r0[1]) * D + lane];
        float ns0 = a0u * ae0[(size_t)(nu + r0[2]) * D + lane];
        float a1u = ae1[(size_t)r1[0] * D + lane];
        float ps1 = a1u * ae1[(size_t)(nu + r1[1]) * D + lane];
        float ns1 = a1u * ae1[(size_t)(nu + r1[2]) * D + lane];
        #pragma unroll
        for (int o = 16; o; o >>= 1) {
            pp0 += __shfl_xor_sync(0xffffffffu, pp0, o);
            nn0 += __shfl_xor_sync(0xffffffffu, nn0, o);
            pp1 += __shfl_xor_sync(0xffffffffu, pp1, o);
            nn1 += __shfl_xor_sync(0xffffffffu, nn1, o);
            ps0 += __shfl_xor_sync(0xffffffffu, ps0, o);
            ns0 += __shfl_xor_sync(0xffffffffu, ns0, o);
            ps1 += __shfl_xor_sync(0xffffffffu, ps1, o);
            ns1 += __shfl_xor_sync(0xffffffffu, ns1, o);
        }
        if (lane == 0) {
            g_sc[4 * BMAX + warp] = fmaxf(pp0, 0.f);
            g_sc[6 * BMAX + warp] = fmaxf(nn0, 0.f);
            g_sc[5 * BMAX + warp] = fmaxf(pp1, 0.f);
            g_sc[7 * BMAX + warp] = fmaxf(nn1, 0.f);
        }
        val0 = logsig(ps0 - ns0);
        val1 = logsig(ps1 - ns1);
    }
    if (lane == 0) { sh0[wid] = val0; sh1[wid] = val1; }
    __syncthreads();
    if (threadIdx.x < 32) {
        float v0 = (threadIdx.x < (blockDim.x >> 5)) ? sh0[threadIdx.x] : 0.f;
        float v1 = (threadIdx.x < (blockDim.x >> 5)) ? sh1[threadIdx.x] : 0.f;
        #pragma unroll
        for (int o = 16; o; o >>= 1) {
            v0 += __shfl_xor_sync(0xffffffffu, v0, o);
            v1 += __shfl_xor_sync(0xffffffffu, v1, o);
        }
        if (threadIdx.x == 0) {
            atomicAdd(&g_scal[0], v0);
            atomicAdd(&g_scal[1], v1);
        }
    }
}

__global__ void k_sumsq2(const float* __restrict__ u, int nuD,
                         const float* __restrict__ it, int niD) {
    __shared__ float sh[8];
    const float* x = blockIdx.y ? it : u;
    int n = blockIdx.y ? niD : nuD;
    int slot = blockIdx.y ? 3 : 2;
    float local = 0.f;
    for (int i = blockIdx.x * blockDim.x + threadIdx.x; i < n; i += gridDim.x * blockDim.x) {
        float v = x[i];
        local += v * v;
    }
    int lane = threadIdx.x & 31, wid = threadIdx.x >> 5;
    #pragma unroll
    for (int o = 16; o; o >>= 1) local += __shfl_xor_sync(0xffffffffu, local, o);
    if (lane == 0) sh[wid] = local;
    __syncthreads();
    if (threadIdx.x < 32) {
        float v = (threadIdx.x < (blockDim.x >> 5)) ? sh[threadIdx.x] : 0.f;
        #pragma unroll
        for (int o = 16; o; o >>= 1) v += __shfl_xor_sync(0xffffffffu, v, o);
        if (threadIdx.x == 0) atomicAdd(&g_scal[slot], v);
    }
}

__global__ void k_final(int B, int ni, float* __restrict__ out) {
    __shared__ float sh[8];
    float local = 0.f;
    for (int b = threadIdx.x; b < B; b += blockDim.x) {
        float cp0 = g_sc[ 0 * BMAX + b], cp1 = g_sc[ 1 * BMAX + b];
        float cn0 = g_sc[ 2 * BMAX + b], cn1 = g_sc[ 3 * BMAX + b];
        float ap0 = g_sc[ 4 * BMAX + b], ap1 = g_sc[ 5 * BMAX + b];
        float an0 = g_sc[ 6 * BMAX + b], an1 = g_sc[ 7 * BMAX + b];
        float dp0 = g_sc[ 8 * BMAX + b], dp1 = g_sc[ 9 * BMAX + b];
        float dn0 = g_sc[10 * BMAX + b], dn1 = g_sc[11 * BMAX + b];
        float ps = (dp0 + dp1) * (cp0 * ap0 + cp1 * ap1);
        float ns = (dn0 + dn1) * (cn0 * an0 + cn1 * an1);
        local += logsig(ps - ns);
    }
    int lane = threadIdx.x & 31, wid = threadIdx.x >> 5;
    #pragma unroll
    for (int o = 16; o; o >>= 1) local += __shfl_xor_sync(0xffffffffu, local, o);
    if (lane == 0) sh[wid] = local;
    __syncthreads();
    if (threadIdx.x == 0) {
        float s = 0.f;
        for (int i = 0; i < (int)(blockDim.x >> 5); i++) s += sh[i];
        float rec  = -s / (float)B;
        float aux  = -(g_scal[0] + g_scal[1]) / (2.f * (float)B);
        float embl = (sqrtf(g_scal[2]) + sqrtf(g_scal[3])) / (float)ni;
        out[0] = rec + 0.5f * aux + 1e-4f * embl;
    }
}

// ---------------------------------------------------------------------------
// Host orchestration (graph-capturable, fork/join dual stream)
// ---------------------------------------------------------------------------
#define TB 256
static inline int nblk(long long n) { return (int)((n + TB - 1) / TB); }

extern "C" void kernel_launch(void* const* d_in, const int* in_sizes, int n_in,
                              void* d_out, int out_size) {
    static cudaStream_t s1 = 0;
    static cudaEvent_t e0 = 0, e1 = 0, e2 = 0, e3 = 0;
    if (!s1) {
        cudaStreamCreateWithFlags(&s1, cudaStreamNonBlocking);
        cudaEventCreateWithFlags(&e0, cudaEventDisableTiming);
        cudaEventCreateWithFlags(&e1, cudaEventDisableTiming);
        cudaEventCreateWithFlags(&e2, cudaEventDisableTiming);
        cudaEventCreateWithFlags(&e3, cudaEventDisableTiming);
    }

    const float* user  = (const float*)d_in[0];
    const float* item  = (const float*)d_in[1];
    const int*   batch = (const int*)  d_in[2];
    const int2*  aux   = (const int2*) d_in[3];
    const int2*  tgt   = (const int2*) d_in[4];

    const int nu   = in_sizes[0] / D;
    const int ni   = in_sizes[1] / D;
    const int ntot = nu + ni;
    const int B    = in_sizes[2] / 9;
    const int Ea   = in_sizes[3] / 4;
    const int Et   = in_sizes[4] / 2;

    float *emb, *pc0, *pc1, *ae0, *ae1, *a0, *a1, *dnv;
    int *degi, *off, *curs;
    float4* csr;
    void* p;
    cudaGetSymbolAddress(&p, g_emb);  emb = (float*)p;
    cudaGetSymbolAddress(&p, g_pc0);  pc0 = (float*)p;
    cudaGetSymbolAddress(&p, g_pc1);  pc1 = (float*)p;
    cudaGetSymbolAddress(&p, g_ae0);  ae0 = (float*)p;
    cudaGetSymbolAddress(&p, g_ae1);  ae1 = (float*)p;
    cudaGetSymbolAddress(&p, g_a0);   a0  = (float*)p;
    cudaGetSymbolAddress(&p, g_a1);   a1  = (float*)p;
    cudaGetSymbolAddress(&p, g_dnv);  dnv = (float*)p;
    cudaGetSymbolAddress(&p, g_degi); degi = (int*)p;
    cudaGetSymbolAddress(&p, g_off);  off  = (int*)p;
    cudaGetSymbolAddress(&p, g_curs); curs = (int*)p;
    cudaGetSymbolAddress(&p, g_csr);  csr  = (float4*)p;
    void* scalp; cudaGetSymbolAddress(&scalp, g_scal);

    const float* wC0 = dnv + 0 * NTOT_C;
    const float* wC1 = dnv + 1 * NTOT_C;
    const float* wT  = dnv + 4 * NTOT_C;

    // ---- init + fork sumsq to side stream ----
    cudaMemsetAsync(scalp, 0, 4 * sizeof(float), 0);
    cudaEventRecord(e0, 0);
    cudaStreamWaitEvent(s1, e0, 0);
    {
        dim3 g(512, 2);
        k_sumsq2<<<g, TB, 0, s1>>>(user, nu * D, item, ni * D);
    }
    cudaMemcpyAsync(emb, user, (size_t)nu * D * sizeof(float), cudaMemcpyDeviceToDevice, 0);
    cudaMemcpyAsync(emb + (size_t)nu * D, item, (size_t)ni * D * sizeof(float),
                    cudaMemcpyDeviceToDevice, 0);

    // ---- build ----
    cudaMemsetAsync(degi, 0, 3 * NTOT_C * sizeof(int), 0);
    k_deg3<<<nblk(2LL * Ea + Et), TB>>>(aux, tgt, Ea, Et, nu);
    k_dinv5<<<nblk(NTOT_C), TB>>>();
    dim3 gScan(NBLK_SCAN, 3);
    k_scanA<<<gScan, SCAN_B>>>();
    k_scanB<<<3, 1024>>>(NBLK_SCAN);
    k_scanC<<<gScan, SCAN_B>>>();
    cudaMemcpyAsync(curs, off, 3 * NOFF * sizeof(int), cudaMemcpyDeviceToDevice, 0);
    k_fill3<<<nblk(2LL * Ea + Et), TB>>>(aux, tgt, Ea, Et, nu);

    const long long bA0 = 0, bA1 = 2LL * Ea, bT = 4LL * Ea;
    const int* offA0 = off + 0 * NOFF;
    const int* offA1 = off + 1 * NOFF;
    const int* offT  = off + 2 * NOFF;
    const int gcnB = nblk((long long)ntot * 32);
    const int sblk = nblk((long long)B * 32);

    // ---- layer-1: both aux passes in one launch, then tgt accumulate ----
    {
        dim3 g(gcnB, 2);
        k_l1aux<<<g, TB>>>(csr + bA0, offA0, csr + bA1, offA1, emb,
                           pc0, a0, pc1, a1, ntot);
    }
    k_l1tgt<<<gcnB, TB>>>(csr + bT, offT, emb, pc0, pc1, ntot);

    // fork comb scoring to side stream
    cudaEventRecord(e1, 0);
    cudaStreamWaitEvent(s1, e1, 0);
    {
        dim3 g(sblk, 2);
        k_score_comb<<<g, TB, 0, s1>>>(csr + bA0, offA0, csr + bA1, offA1,
                                       csr + bT, offT, wC0, wC1, pc0, pc1, emb,
                                       batch, B, nu);
    }

    // ---- aux layer-2 -> ae (both graphs, one launch) ----
    {
        dim3 g(gcnB, 2);
        k_gcn2<<<g, TB>>>(csr + bA0, offA0, csr + bA1, offA1, a0, a1, emb,
                          ae0, ae1, ntot);
    }

    // fork aux scores to side stream
    cudaEventRecord(e2, 0);
    cudaStreamWaitEvent(s1, e2, 0);
    k_scores_aux2<<<sblk, TB, 0, s1>>>(ae0, ae1, batch, B, nu);

    // ---- de layer-1 (dual source; reuse a buffers) + de scoring ----
    float* d0 = a0;
    float* d1 = a1;
    k_dual_s<<<gcnB, TB>>>(csr + bT, offT, ae0, ae1, wT, d0, d1, ntot);
    k_score_de<<<sblk, TB>>>(csr + bT, offT, wT, d0, d1, ae0, ae1, batch, B, nu);

    // ---- join + finalize ----
    cudaEventRecord(e3, s1);
    cudaStreamWaitEvent(0, e3, 0);
    k_final<<<1, TB>>>(B, ni, (float*)d_out);
}

// round 14
// speedup vs baseline: 1.4329x; 1.4329x over previous
#include <cuda_runtime.h>
#include <math.h>

// ---------------------------------------------------------------------------
// Shapes
// ---------------------------------------------------------------------------
#define D        32
#define NU_C     100001
#define NI_C     50001
#define NTOT_C   (NU_C + NI_C)          // 150002
#define NOFF     (NTOT_C + 1)
#define BMAX     4096
#define SCAN_B   256
#define NBLK_SCAN ((NOFF + SCAN_B - 1) / SCAN_B)
#define SUMS_STRIDE 640
#define CSR_CAP  6400000

// ---------------------------------------------------------------------------
// Device scratch
// ---------------------------------------------------------------------------
__device__ float g_emb[NTOT_C * D];
__device__ float g_pc0[NTOT_C * D];     // comb0 layer1
__device__ float g_pc1[NTOT_C * D];     // comb1 layer1
__device__ float g_ae0[NTOT_C * D];     // ae0
__device__ float g_ae1[NTOT_C * D];     // ae1
__device__ float g_a0 [NTOT_C * D];     // aux0 layer1; later de0 layer1
__device__ float g_a1 [NTOT_C * D];     // aux1 layer1; later de1 layer1
__device__ int    g_degi [3 * NTOT_C];  // aux0, aux1, tgt
__device__ float  g_dnv  [5 * NTOT_C];  // SoA: c0, c1, a0, a1, t
__device__ float2 g_dnv2 [3 * NTOT_C];  // pairs: (c0,a0), (c1,a1), (c0,c1)
__device__ int   g_off  [3 * NOFF];
__device__ int   g_curs [3 * NOFF];
__device__ int   g_bsums[3 * SUMS_STRIDE];
__device__ int   g_csr  [CSR_CAP];      // neighbor indices only
// score slots: CP=0 CN=1 AP=2 AN=3 DP=4 DN=5; offset = (slot*2 + idx)*BMAX + b
__device__ float g_sc  [12 * BMAX];
__device__ float g_scal[4];

// ---------------------------------------------------------------------------
// Helpers
// ---------------------------------------------------------------------------
__device__ __forceinline__ float logsig(float x) {
    return (x >= 0.f) ? -log1pf(expf(-x)) : (x - log1pf(expf(x)));
}

// warp-per-row weighted gather (scoring kernels; R10-proven shape)
__device__ __forceinline__ float gather_w(const int* __restrict__ csr,
                                          int k, int end,
                                          const float* __restrict__ dnv,
                                          const float* __restrict__ src,
                                          int lane) {
    float acc = 0.f;
    for (; k + 8 <= end; k += 8) {
        int e[8]; float w[8];
        #pragma unroll
        for (int j = 0; j < 8; j++) e[j] = __ldg(&csr[k + j]);
        #pragma unroll
        for (int j = 0; j < 8; j++) w[j] = __ldg(&dnv[e[j]]);
        #pragma unroll
        for (int j = 0; j < 8; j++)
            acc = fmaf(w[j], __ldg(&src[(size_t)e[j] * D + lane]), acc);
    }
    for (; k < end; k++) {
        int e = __ldg(&csr[k]);
        acc = fmaf(__ldg(&dnv[e]), __ldg(&src[(size_t)e * D + lane]), acc);
    }
    return acc;
}

// ---------------------------------------------------------------------------
// Graph build (identical to R10)
// ---------------------------------------------------------------------------
__global__ void k_deg3(const int2* __restrict__ aux, const int2* __restrict__ tgt,
                       int Ea, int Et, int nu) {
    int t = blockIdx.x * blockDim.x + threadIdx.x;
    int2 ed; int slot;
    if (t < 2 * Ea)            { ed = aux[t];          slot = (t < Ea) ? 0 : 1; }
    else if (t < 2 * Ea + Et)  { ed = tgt[t - 2 * Ea]; slot = 2; }
    else return;
    int* deg = g_degi + slot * NTOT_C;
    atomicAdd(&deg[ed.x], 1);
    atomicAdd(&deg[nu + ed.y], 1);
}

__global__ void k_dinv5() {
    int i = blockIdx.x * blockDim.x + threadIdx.x;
    if (i >= NTOT_C) return;
    int d0 = g_degi[0 * NTOT_C + i];
    int d1 = g_degi[1 * NTOT_C + i];
    int dt = g_degi[2 * NTOT_C + i];
    int dd[5] = {d0 + dt, d1 + dt, d0, d1, dt};
    float w[5];
    #pragma unroll
    for (int s = 0; s < 5; s++) {
        w[s] = (dd[s] > 0) ? rsqrtf((float)dd[s]) : 0.f;
        g_dnv[s * NTOT_C + i] = w[s];
    }
    g_dnv2[0 * NTOT_C + i] = make_float2(w[0], w[2]);  // (c0, a0)
    g_dnv2[1 * NTOT_C + i] = make_float2(w[1], w[3]);  // (c1, a1)
    g_dnv2[2 * NTOT_C + i] = make_float2(w[0], w[1]);  // (c0, c1)
}

__global__ void k_scanA() {
    int g = blockIdx.y;
    const int* deg = g_degi + g * NTOT_C;
    int* out  = g_off   + g * NOFF;
    int* sums = g_bsums + g * SUMS_STRIDE;
    int idx = blockIdx.x * SCAN_B + threadIdx.x;
    int val = (idx < NTOT_C) ? deg[idx] : 0;
    int lane = threadIdx.x & 31, wid = threadIdx.x >> 5;
    int x = val;
    #pragma unroll
    for (int o = 1; o < 32; o <<= 1) {
        int y = __shfl_up_sync(0xffffffffu, x, o);
        if (lane >= o) x += y;
    }
    __shared__ int ws[8], wbase[8];
    if (lane == 31) ws[wid] = x;
    __syncthreads();
    if (threadIdx.x == 0) {
        int s = 0;
        for (int i = 0; i < 8; i++) { wbase[i] = s; s += ws[i]; }
    }
    __syncthreads();
    int incl = x + wbase[wid];
    if (idx < NOFF) out[idx] = incl - val;
    if (threadIdx.x == SCAN_B - 1) sums[blockIdx.x] = incl;
}

__global__ void k_scanB(int nb) {
    int g = blockIdx.x;
    int* sums = g_bsums + g * SUMS_STRIDE;
    __shared__ int sh[SUMS_STRIDE];
    int tid = threadIdx.x;
    int orig = 0;
    if (tid < nb) { orig = sums[tid]; sh[tid] = orig; }
    __syncthreads();
    for (int o = 1; o < nb; o <<= 1) {
        int v = 0;
        if (tid < nb && tid >= o) v = sh[tid - o];
        __syncthreads();
        if (tid < nb && tid >= o) sh[tid] += v;
        __syncthreads();
    }
    if (tid < nb) sums[tid] = sh[tid] - orig;
}

__global__ void k_scanC() {
    int g = blockIdx.y;
    int idx = blockIdx.x * SCAN_B + threadIdx.x;
    if (idx < NOFF)
        g_off[g * NOFF + idx] += g_bsums[g * SUMS_STRIDE + blockIdx.x];
}

__global__ void k_fill3(const int2* __restrict__ aux, const int2* __restrict__ tgt,
                        int Ea, int Et, int nu) {
    int t = blockIdx.x * blockDim.x + threadIdx.x;
    int2 ed; int slot; long long base;
    if (t < 2 * Ea) {
        ed = aux[t];
        slot = (t < Ea) ? 0 : 1;
        base = (t < Ea) ? 0 : 2LL * Ea;
    } else if (t < 2 * Ea + Et) {
        ed = tgt[t - 2 * Ea]; slot = 2; base = 4LL * Ea;
    } else return;
    int* curs = g_curs + slot * NOFF;
    int* csr  = g_csr + base;
    int u = ed.x, v = nu + ed.y;
    csr[atomicAdd(&curs[u], 1)] = v;
    csr[atomicAdd(&curs[v], 1)] = u;
}

// ---------------------------------------------------------------------------
// Propagation — two nodes per warp, float2 columns
// lanes 0-15 -> node 2w, lanes 16-31 -> node 2w+1; each lane covers cols 2s,2s+1
// ---------------------------------------------------------------------------
// paired float2 weights -> two outputs; optional accumulate
__global__ void __launch_bounds__(256)
k_dual_w2(const int* __restrict__ csr, const int* __restrict__ off,
          const float* __restrict__ src,
          const float2* __restrict__ w2,
          const float* __restrict__ wXs, const float* __restrict__ wYs,
          float* __restrict__ outX, float* __restrict__ outY, int ntot, int accum) {
    int w = (blockIdx.x * blockDim.x + threadIdx.x) >> 5;
    int lane = threadIdx.x & 31;
    int half = lane >> 4;
    int sub  = lane & 15;
    int u = 2 * w + half;
    if (u >= ntot) return;
    int k = off[u], end = off[u + 1];
    float2 aX = make_float2(0.f, 0.f), aY = make_float2(0.f, 0.f);
    for (; k < end; k += 8) {
        int e[8]; float2 ww[8];
        #pragma unroll
        for (int j = 0; j < 8; j++) {
            int kk = k + j;
            e[j] = __ldg(&csr[kk < end ? kk : k]);
        }
        #pragma unroll
        for (int j = 0; j < 8; j++)
            ww[j] = (k + j < end) ? __ldg(&w2[e[j]]) : make_float2(0.f, 0.f);
        #pragma unroll
        for (int j = 0; j < 8; j++) {
            float2 v = __ldg((const float2*)(src + (size_t)e[j] * D) + sub);
            aX.x = fmaf(ww[j].x, v.x, aX.x);
            aX.y = fmaf(ww[j].x, v.y, aX.y);
            aY.x = fmaf(ww[j].y, v.x, aY.x);
            aY.y = fmaf(ww[j].y, v.y, aY.y);
        }
    }
    size_t o = (size_t)u * D + 2 * sub;
    float sx = __ldg(&wXs[u]);
    float sy = __ldg(&wYs[u]);
    float2 rx = make_float2(sx * aX.x, sx * aX.y);
    float2 ry = make_float2(sy * aY.x, sy * aY.y);
    if (accum) {
        float2 px = *(const float2*)(outX + o);
        float2 py = *(const float2*)(outY + o);
        rx.x += px.x; rx.y += px.y;
        ry.x += py.x; ry.y += py.y;
    }
    *(float2*)(outX + o) = rx;
    *(float2*)(outY + o) = ry;
}

// aux layer-2: out = (w[u]*gather + src + base)/3, paired nodes
__global__ void __launch_bounds__(256)
k_gcn_w2(const int* __restrict__ csr, const int* __restrict__ off,
         const float* __restrict__ w,
         const float* __restrict__ src, const float* __restrict__ base,
         float* __restrict__ out, int ntot) {
    int wp = (blockIdx.x * blockDim.x + threadIdx.x) >> 5;
    int lane = threadIdx.x & 31;
    int half = lane >> 4;
    int sub  = lane & 15;
    int u = 2 * wp + half;
    if (u >= ntot) return;
    int k = off[u], end = off[u + 1];
    float2 acc = make_float2(0.f, 0.f);
    for (; k < end; k += 8) {
        int e[8]; float ww[8];
        #pragma unroll
        for (int j = 0; j < 8; j++) {
            int kk = k + j;
            e[j] = __ldg(&csr[kk < end ? kk : k]);
        }
        #pragma unroll
        for (int j = 0; j < 8; j++)
            ww[j] = (k + j < end) ? __ldg(&w[e[j]]) : 0.f;
        #pragma unroll
        for (int j = 0; j < 8; j++) {
            float2 v = __ldg((const float2*)(src + (size_t)e[j] * D) + sub);
            acc.x = fmaf(ww[j], v.x, acc.x);
            acc.y = fmaf(ww[j], v.y, acc.y);
        }
    }
    size_t o = (size_t)u * D + 2 * sub;
    float wu = __ldg(&w[u]);
    float2 s = *(const float2*)(src + o);
    float2 b = *(const float2*)(base + o);
    float2 r;
    r.x = (wu * acc.x + s.x + b.x) * (1.f / 3.f);
    r.y = (wu * acc.y + s.y + b.y) * (1.f / 3.f);
    *(float2*)(out + o) = r;
}

// de layer1: one weight vector, two srcs -> two outputs, paired nodes
__global__ void __launch_bounds__(256)
k_dual_s2(const int* __restrict__ csr, const int* __restrict__ off,
          const float* __restrict__ s0, const float* __restrict__ s1,
          const float* __restrict__ w,
          float* __restrict__ o0, float* __restrict__ o1, int ntot) {
    int wp = (blockIdx.x * blockDim.x + threadIdx.x) >> 5;
    int lane = threadIdx.x & 31;
    int half = lane >> 4;
    int sub  = lane & 15;
    int u = 2 * wp + half;
    if (u >= ntot) return;
    int k = off[u], end = off[u + 1];
    float2 a0 = make_float2(0.f, 0.f), a1 = make_float2(0.f, 0.f);
    for (; k < end; k += 8) {
        int e[8]; float ww[8];
        #pragma unroll
        for (int j = 0; j < 8; j++) {
            int kk = k + j;
            e[j] = __ldg(&csr[kk < end ? kk : k]);
        }
        #pragma unroll
        for (int j = 0; j < 8; j++)
            ww[j] = (k + j < end) ? __ldg(&w[e[j]]) : 0.f;
        #pragma unroll
        for (int j = 0; j < 8; j++) {
            size_t rb = (size_t)e[j] * D;
            float2 v0 = __ldg((const float2*)(s0 + rb) + sub);
            float2 v1 = __ldg((const float2*)(s1 + rb) + sub);
            a0.x = fmaf(ww[j], v0.x, a0.x);
            a0.y = fmaf(ww[j], v0.y, a0.y);
            a1.x = fmaf(ww[j], v1.x, a1.x);
            a1.y = fmaf(ww[j], v1.y, a1.y);
        }
    }
    size_t o = (size_t)u * D + 2 * sub;
    float wu = __ldg(&w[u]);
    *(float2*)(o0 + o) = make_float2(wu * a0.x, wu * a0.y);
    *(float2*)(o1 + o) = make_float2(wu * a1.x, wu * a1.y);
}

// ---------------------------------------------------------------------------
// Scoring (identical to R10)
// ---------------------------------------------------------------------------
__global__ void k_score_comb(const int* __restrict__ csrA0, const int* __restrict__ offA0,
                             const int* __restrict__ csrA1, const int* __restrict__ offA1,
                             const int* __restrict__ csrT, const int* __restrict__ offT,
                             const float* __restrict__ w0, const float* __restrict__ w1,
                             const float* __restrict__ nxt0, const float* __restrict__ nxt1,
                             const float* __restrict__ base,
                             const int* __restrict__ batch, int B, int nu) {
    int which = blockIdx.y;
    const int* csrA = which ? csrA1 : csrA0;
    const int* offA = which ? offA1 : offA0;
    const float* w   = which ? w1 : w0;
    const float* nxt = which ? nxt1 : nxt0;
    int wp = (blockIdx.x * blockDim.x + threadIdx.x) >> 5;
    if (wp >= B) return;
    int lane = threadIdx.x & 31;
    const int* row = batch + (size_t)wp * 9;
    int nd[3] = {row[0], nu + row[1], nu + row[2]};
    float val[3];
    #pragma unroll
    for (int t = 0; t < 3; t++) {
        int r = nd[t];
        float g = gather_w(csrA, offA[r], offA[r + 1], w, nxt, lane)
                + gather_w(csrT, offT[r], offT[r + 1], w, nxt, lane);
        size_t o = (size_t)r * D + lane;
        val[t] = base[o] + nxt[o] + __ldg(&w[r]) * g;
    }
    float pp = val[0] * val[1], nn = val[0] * val[2];
    #pragma unroll
    for (int o = 16; o; o >>= 1) {
        pp += __shfl_xor_sync(0xffffffffu, pp, o);
        nn += __shfl_xor_sync(0xffffffffu, nn, o);
    }
    if (lane == 0) {
        g_sc[(0 * 2 + which) * BMAX + wp] = fmaxf(pp * (1.f / 9.f), 0.f);
        g_sc[(1 * 2 + which) * BMAX + wp] = fmaxf(nn * (1.f / 9.f), 0.f);
    }
}

__global__ void k_score_de(const int* __restrict__ csrT, const int* __restrict__ offT,
                           const float* __restrict__ wT,
                           const float* __restrict__ d0, const float* __restrict__ d1,
                           const float* __restrict__ ae0, const float* __restrict__ ae1,
                           const int* __restrict__ batch, int B, int nu) {
    int wp = (blockIdx.x * blockDim.x + threadIdx.x) >> 5;
    if (wp >= B) return;
    int lane = threadIdx.x & 31;
    const int* row = batch + (size_t)wp * 9;
    int nd[3] = {row[0], nu + row[1], nu + row[2]};
    float v0[3], v1[3];
    #pragma unroll
    for (int t = 0; t < 3; t++) {
        int r = nd[t];
        int k = offT[r], end = offT[r + 1];
        float a0 = 0.f, a1 = 0.f;
        for (; k + 8 <= end; k += 8) {
            int e[8]; float wj[8];
            #pragma unroll
            for (int j = 0; j < 8; j++) e[j] = __ldg(&csrT[k + j]);
            #pragma unroll
            for (int j = 0; j < 8; j++) wj[j] = __ldg(&wT[e[j]]);
            #pragma unroll
            for (int j = 0; j < 8; j++) {
                size_t ro = (size_t)e[j] * D + lane;
                a0 = fmaf(wj[j], __ldg(&d0[ro]), a0);
                a1 = fmaf(wj[j], __ldg(&d1[ro]), a1);
            }
        }
        for (; k < end; k++) {
            int e = __ldg(&csrT[k]);
            float wj = __ldg(&wT[e]);
            size_t ro = (size_t)e * D + lane;
            a0 = fmaf(wj, __ldg(&d0[ro]), a0);
            a1 = fmaf(wj, __ldg(&d1[ro]), a1);
        }
        size_t o = (size_t)r * D + lane;
        float wr = __ldg(&wT[r]);
        v0[t] = ae0[o] + d0[o] + wr * a0;
        v1[t] = ae1[o] + d1[o] + wr * a1;
    }
    float pp0 = v0[0] * v0[1], nn0 = v0[0] * v0[2];
    float pp1 = v1[0] * v1[1], nn1 = v1[0] * v1[2];
    #pragma unroll
    for (int o = 16; o; o >>= 1) {
        pp0 += __shfl_xor_sync(0xffffffffu, pp0, o);
        nn0 += __shfl_xor_sync(0xffffffffu, nn0, o);
        pp1 += __shfl_xor_sync(0xffffffffu, pp1, o);
        nn1 += __shfl_xor_sync(0xffffffffu, nn1, o);
    }
    if (lane == 0) {
        g_sc[ 8 * BMAX + wp] = fmaxf(pp0 * (1.f / 9.f), 0.f);
        g_sc[10 * BMAX + wp] = fmaxf(nn0 * (1.f / 9.f), 0.f);
        g_sc[ 9 * BMAX + wp] = fmaxf(pp1 * (1.f / 9.f), 0.f);
        g_sc[11 * BMAX + wp] = fmaxf(nn1 * (1.f / 9.f), 0.f);
    }
}

__global__ void k_scores_aux2(const float* __restrict__ ae0, const float* __restrict__ ae1,
                              const int* __restrict__ batch, int B, int nu) {
    __shared__ float sh0[8], sh1[8];
    int warp = (blockIdx.x * blockDim.x + threadIdx.x) >> 5;
    int lane = threadIdx.x & 31;
    int wid  = threadIdx.x >> 5;
    float val0 = 0.f, val1 = 0.f;
    if (warp < B) {
        const int* row = batch + (size_t)warp * 9;
        int u = row[0], p = nu + row[1], n = nu + row[2];
        size_t ou = (size_t)u * D + lane, op = (size_t)p * D + lane, on = (size_t)n * D + lane;
        float e0u = ae0[ou], e1u = ae1[ou];
        float pp0 = e0u * ae0[op], nn0 = e0u * ae0[on];
        float pp1 = e1u * ae1[op], nn1 = e1u * ae1[on];
        const int* r0 = row + 3;
        const int* r1 = row + 6;
        float a0u = ae0[(size_t)r0[0] * D + lane];
        float ps0 = a0u * ae0[(size_t)(nu + r0[1]) * D + lane];
        float ns0 = a0u * ae0[(size_t)(nu + r0[2]) * D + lane];
        float a1u = ae1[(size_t)r1[0] * D + lane];
        float ps1 = a1u * ae1[(size_t)(nu + r1[1]) * D + lane];
        float ns1 = a1u * ae1[(size_t)(nu + r1[2]) * D + lane];
        #pragma unroll
        for (int o = 16; o; o >>= 1) {
            pp0 += __shfl_xor_sync(0xffffffffu, pp0, o);
            nn0 += __shfl_xor_sync(0xffffffffu, nn0, o);
            pp1 += __shfl_xor_sync(0xffffffffu, pp1, o);
            nn1 += __shfl_xor_sync(0xffffffffu, nn1, o);
            ps0 += __shfl_xor_sync(0xffffffffu, ps0, o);
            ns0 += __shfl_xor_sync(0xffffffffu, ns0, o);
            ps1 += __shfl_xor_sync(0xffffffffu, ps1, o);
            ns1 += __shfl_xor_sync(0xffffffffu, ns1, o);
        }
        if (lane == 0) {
            g_sc[4 * BMAX + warp] = fmaxf(pp0, 0.f);
            g_sc[6 * BMAX + warp] = fmaxf(nn0, 0.f);
            g_sc[5 * BMAX + warp] = fmaxf(pp1, 0.f);
            g_sc[7 * BMAX + warp] = fmaxf(nn1, 0.f);
        }
        val0 = logsig(ps0 - ns0);
        val1 = logsig(ps1 - ns1);
    }
    if (lane == 0) { sh0[wid] = val0; sh1[wid] = val1; }
    __syncthreads();
    if (threadIdx.x < 32) {
        float v0 = (threadIdx.x < (blockDim.x >> 5)) ? sh0[threadIdx.x] : 0.f;
        float v1 = (threadIdx.x < (blockDim.x >> 5)) ? sh1[threadIdx.x] : 0.f;
        #pragma unroll
        for (int o = 16; o; o >>= 1) {
            v0 += __shfl_xor_sync(0xffffffffu, v0, o);
            v1 += __shfl_xor_sync(0xffffffffu, v1, o);
        }
        if (threadIdx.x == 0) {
            atomicAdd(&g_scal[0], v0);
            atomicAdd(&g_scal[1], v1);
        }
    }
}

__global__ void k_sumsq2(const float* __restrict__ u, int nuD,
                         const float* __restrict__ it, int niD) {
    __shared__ float sh[8];
    const float* x = blockIdx.y ? it : u;
    int n = blockIdx.y ? niD : nuD;
    int slot = blockIdx.y ? 3 : 2;
    float local = 0.f;
    for (int i = blockIdx.x * blockDim.x + threadIdx.x; i < n; i += gridDim.x * blockDim.x) {
        float v = x[i];
        local += v * v;
    }
    int lane = threadIdx.x & 31, wid = threadIdx.x >> 5;
    #pragma unroll
    for (int o = 16; o; o >>= 1) local += __shfl_xor_sync(0xffffffffu, local, o);
    if (lane == 0) sh[wid] = local;
    __syncthreads();
    if (threadIdx.x < 32) {
        float v = (threadIdx.x < (blockDim.x >> 5)) ? sh[threadIdx.x] : 0.f;
        #pragma unroll
        for (int o = 16; o; o >>= 1) v += __shfl_xor_sync(0xffffffffu, v, o);
        if (threadIdx.x == 0) atomicAdd(&g_scal[slot], v);
    }
}

__global__ void k_final(int B, int ni, float* __restrict__ out) {
    __shared__ float sh[8];
    float local = 0.f;
    for (int b = threadIdx.x; b < B; b += blockDim.x) {
        float cp0 = g_sc[ 0 * BMAX + b], cp1 = g_sc[ 1 * BMAX + b];
        float cn0 = g_sc[ 2 * BMAX + b], cn1 = g_sc[ 3 * BMAX + b];
        float ap0 = g_sc[ 4 * BMAX + b], ap1 = g_sc[ 5 * BMAX + b];
        float an0 = g_sc[ 6 * BMAX + b], an1 = g_sc[ 7 * BMAX + b];
        float dp0 = g_sc[ 8 * BMAX + b], dp1 = g_sc[ 9 * BMAX + b];
        float dn0 = g_sc[10 * BMAX + b], dn1 = g_sc[11 * BMAX + b];
        float ps = (dp0 + dp1) * (cp0 * ap0 + cp1 * ap1);
        float ns = (dn0 + dn1) * (cn0 * an0 + cn1 * an1);
        local += logsig(ps - ns);
    }
    int lane = threadIdx.x & 31, wid = threadIdx.x >> 5;
    #pragma unroll
    for (int o = 16; o; o >>= 1) local += __shfl_xor_sync(0xffffffffu, local, o);
    if (lane == 0) sh[wid] = local;
    __syncthreads();
    if (threadIdx.x == 0) {
        float s = 0.f;
        for (int i = 0; i < (int)(blockDim.x >> 5); i++) s += sh[i];
        float rec  = -s / (float)B;
        float aux  = -(g_scal[0] + g_scal[1]) / (2.f * (float)B);
        float embl = (sqrtf(g_scal[2]) + sqrtf(g_scal[3])) / (float)ni;
        out[0] = rec + 0.5f * aux + 1e-4f * embl;
    }
}

// ---------------------------------------------------------------------------
// Host orchestration (graph-capturable, fork/join dual stream; R10 structure)
// ---------------------------------------------------------------------------
#define TB 256
static inline int nblk(long long n) { return (int)((n + TB - 1) / TB); }

extern "C" void kernel_launch(void* const* d_in, const int* in_sizes, int n_in,
                              void* d_out, int out_size) {
    static cudaStream_t s1 = 0;
    static cudaEvent_t e0 = 0, e1 = 0, e2 = 0, e3 = 0;
    if (!s1) {
        cudaStreamCreateWithFlags(&s1, cudaStreamNonBlocking);
        cudaEventCreateWithFlags(&e0, cudaEventDisableTiming);
        cudaEventCreateWithFlags(&e1, cudaEventDisableTiming);
        cudaEventCreateWithFlags(&e2, cudaEventDisableTiming);
        cudaEventCreateWithFlags(&e3, cudaEventDisableTiming);
    }

    const float* user  = (const float*)d_in[0];
    const float* item  = (const float*)d_in[1];
    const int*   batch = (const int*)  d_in[2];
    const int2*  aux   = (const int2*) d_in[3];
    const int2*  tgt   = (const int2*) d_in[4];

    const int nu   = in_sizes[0] / D;
    const int ni   = in_sizes[1] / D;
    const int ntot = nu + ni;
    const int B    = in_sizes[2] / 9;
    const int Ea   = in_sizes[3] / 4;
    const int Et   = in_sizes[4] / 2;

    float *emb, *pc0, *pc1, *ae0, *ae1, *a0, *a1, *dnv;
    float2* dnv2;
    int *degi, *off, *curs, *csr;
    void* p;
    cudaGetSymbolAddress(&p, g_emb);  emb = (float*)p;
    cudaGetSymbolAddress(&p, g_pc0);  pc0 = (float*)p;
    cudaGetSymbolAddress(&p, g_pc1);  pc1 = (float*)p;
    cudaGetSymbolAddress(&p, g_ae0);  ae0 = (float*)p;
    cudaGetSymbolAddress(&p, g_ae1);  ae1 = (float*)p;
    cudaGetSymbolAddress(&p, g_a0);   a0  = (float*)p;
    cudaGetSymbolAddress(&p, g_a1);   a1  = (float*)p;
    cudaGetSymbolAddress(&p, g_dnv);  dnv = (float*)p;
    cudaGetSymbolAddress(&p, g_dnv2); dnv2 = (float2*)p;
    cudaGetSymbolAddress(&p, g_degi); degi = (int*)p;
    cudaGetSymbolAddress(&p, g_off);  off  = (int*)p;
    cudaGetSymbolAddress(&p, g_curs); curs = (int*)p;
    cudaGetSymbolAddress(&p, g_csr);  csr  = (int*)p;
    void* scalp; cudaGetSymbolAddress(&scalp, g_scal);

    const float* wC0 = dnv + 0 * NTOT_C;
    const float* wC1 = dnv + 1 * NTOT_C;
    const float* wA0 = dnv + 2 * NTOT_C;
    const float* wA1 = dnv + 3 * NTOT_C;
    const float* wT  = dnv + 4 * NTOT_C;

    // ---- init + fork sumsq to side stream ----
    cudaMemsetAsync(scalp, 0, 4 * sizeof(float), 0);
    cudaEventRecord(e0, 0);
    cudaStreamWaitEvent(s1, e0, 0);
    {
        dim3 g(512, 2);
        k_sumsq2<<<g, TB, 0, s1>>>(user, nu * D, item, ni * D);
    }
    cudaMemcpyAsync(emb, user, (size_t)nu * D * sizeof(float), cudaMemcpyDeviceToDevice, 0);
    cudaMemcpyAsync(emb + (size_t)nu * D, item, (size_t)ni * D * sizeof(float),
                    cudaMemcpyDeviceToDevice, 0);

    // ---- build ----
    cudaMemsetAsync(degi, 0, 3 * NTOT_C * sizeof(int), 0);
    k_deg3<<<nblk(2LL * Ea + Et), TB>>>(aux, tgt, Ea, Et, nu);
    k_dinv5<<<nblk(NTOT_C), TB>>>();
    dim3 gScan(NBLK_SCAN, 3);
    k_scanA<<<gScan, SCAN_B>>>();
    k_scanB<<<3, 1024>>>(NBLK_SCAN);
    k_scanC<<<gScan, SCAN_B>>>();
    cudaMemcpyAsync(curs, off, 3 * NOFF * sizeof(int), cudaMemcpyDeviceToDevice, 0);
    k_fill3<<<nblk(2LL * Ea + Et), TB>>>(aux, tgt, Ea, Et, nu);

    const long long bA0 = 0, bA1 = 2LL * Ea, bT = 4LL * Ea;
    const int* offA0 = off + 0 * NOFF;
    const int* offA1 = off + 1 * NOFF;
    const int* offT  = off + 2 * NOFF;
    const int npair = (ntot + 1) / 2;
    const int gcnB2 = nblk((long long)npair * 32);
    const int sblk  = nblk((long long)B * 32);

    // ---- layer-1 (paired-node dual-weight; tgt pass accumulates) ----
    k_dual_w2<<<gcnB2, TB>>>(csr + bA0, offA0, emb, dnv2 + 0 * NTOT_C, wC0, wA0,
                             pc0, a0, ntot, 0);
    k_dual_w2<<<gcnB2, TB>>>(csr + bA1, offA1, emb, dnv2 + 1 * NTOT_C, wC1, wA1,
                             pc1, a1, ntot, 0);
    k_dual_w2<<<gcnB2, TB>>>(csr + bT,  offT,  emb, dnv2 + 2 * NTOT_C, wC0, wC1,
                             pc0, pc1, ntot, 1);

    // fork comb scoring to side stream
    cudaEventRecord(e1, 0);
    cudaStreamWaitEvent(s1, e1, 0);
    {
        dim3 g(sblk, 2);
        k_score_comb<<<g, TB, 0, s1>>>(csr + bA0, offA0, csr + bA1, offA1,
                                       csr + bT, offT, wC0, wC1, pc0, pc1, emb,
                                       batch, B, nu);
    }

    // ---- aux layer-2 -> ae (paired nodes) ----
    k_gcn_w2<<<gcnB2, TB>>>(csr + bA0, offA0, wA0, a0, emb, ae0, ntot);
    k_gcn_w2<<<gcnB2, TB>>>(csr + bA1, offA1, wA1, a1, emb, ae1, ntot);

    // fork aux scores to side stream
    cudaEventRecord(e2, 0);
    cudaStreamWaitEvent(s1, e2, 0);
    k_scores_aux2<<<sblk, TB, 0, s1>>>(ae0, ae1, batch, B, nu);

    // ---- de layer-1 (paired nodes, dual source) + de scoring ----
    float* d0 = a0;
    float* d1 = a1;
    k_dual_s2<<<gcnB2, TB>>>(csr + bT, offT, ae0, ae1, wT, d0, d1, ntot);
    k_score_de<<<sblk, TB>>>(csr + bT, offT, wT, d0, d1, ae0, ae1, batch, B, nu);

    // ---- join + finalize ----
    cudaEventRecord(e3, s1);
    cudaStreamWaitEvent(0, e3, 0);
    k_final<<<1, TB>>>(B, ni, (float*)d_out);
}

// round 15
// speedup vs baseline: 1.6131x; 1.1258x over previous
#include <cuda_runtime.h>
#include <math.h>

// ---------------------------------------------------------------------------
// Shapes
// ---------------------------------------------------------------------------
#define D        32
#define NU_C     100001
#define NI_C     50001
#define NTOT_C   (NU_C + NI_C)          // 150002
#define NOFF     (NTOT_C + 1)
#define BMAX     4096
#define SCAN_B   256
#define NBLK_SCAN ((NOFF + SCAN_B - 1) / SCAN_B)
#define SUMS_STRIDE 640
#define CSR_CAP  6400000

// ---------------------------------------------------------------------------
// Device scratch
// ---------------------------------------------------------------------------
__device__ float g_emb[NTOT_C * D];
__device__ float g_pc0[NTOT_C * D];     // comb0 layer1
__device__ float g_pc1[NTOT_C * D];     // comb1 layer1
__device__ float g_ae0[NTOT_C * D];     // ae0
__device__ float g_ae1[NTOT_C * D];     // ae1
__device__ float g_a0 [NTOT_C * D];     // aux0 layer1; later de0 layer1
__device__ float g_a1 [NTOT_C * D];     // aux1 layer1; later de1 layer1
__device__ int    g_degi [3 * NTOT_C];  // aux0, aux1, tgt
__device__ float  g_dnv  [5 * NTOT_C];  // SoA: c0, c1, a0, a1, t
__device__ float2 g_dnv2 [3 * NTOT_C];  // pairs: (c0,a0), (c1,a1), (c0,c1)
__device__ int   g_off  [3 * NOFF];
__device__ int   g_curs [3 * NOFF];
__device__ int   g_bsums[3 * SUMS_STRIDE];
__device__ int   g_csr  [CSR_CAP];      // neighbor indices only
// score slots: CP=0 CN=1 AP=2 AN=3 DP=4 DN=5; offset = (slot*2 + idx)*BMAX + b
__device__ float g_sc  [12 * BMAX];
__device__ float g_scal[4];

// ---------------------------------------------------------------------------
// Helpers
// ---------------------------------------------------------------------------
__device__ __forceinline__ float logsig(float x) {
    return (x >= 0.f) ? -log1pf(expf(-x)) : (x - log1pf(expf(x)));
}

// warp-per-row weighted gather (scoring kernels; R10-proven shape)
__device__ __forceinline__ float gather_w(const int* __restrict__ csr,
                                          int k, int end,
                                          const float* __restrict__ dnv,
                                          const float* __restrict__ src,
                                          int lane) {
    float acc = 0.f;
    for (; k + 8 <= end; k += 8) {
        int e[8]; float w[8];
        #pragma unroll
        for (int j = 0; j < 8; j++) e[j] = __ldg(&csr[k + j]);
        #pragma unroll
        for (int j = 0; j < 8; j++) w[j] = __ldg(&dnv[e[j]]);
        #pragma unroll
        for (int j = 0; j < 8; j++)
            acc = fmaf(w[j], __ldg(&src[(size_t)e[j] * D + lane]), acc);
    }
    for (; k < end; k++) {
        int e = __ldg(&csr[k]);
        acc = fmaf(__ldg(&dnv[e]), __ldg(&src[(size_t)e * D + lane]), acc);
    }
    return acc;
}

// ---------------------------------------------------------------------------
// Graph build (identical to R10)
// ---------------------------------------------------------------------------
__global__ void k_deg3(const int2* __restrict__ aux, const int2* __restrict__ tgt,
                       int Ea, int Et, int nu) {
    int t = blockIdx.x * blockDim.x + threadIdx.x;
    int2 ed; int slot;
    if (t < 2 * Ea)            { ed = aux[t];          slot = (t < Ea) ? 0 : 1; }
    else if (t < 2 * Ea + Et)  { ed = tgt[t - 2 * Ea]; slot = 2; }
    else return;
    int* deg = g_degi + slot * NTOT_C;
    atomicAdd(&deg[ed.x], 1);
    atomicAdd(&deg[nu + ed.y], 1);
}

__global__ void k_dinv5() {
    int i = blockIdx.x * blockDim.x + threadIdx.x;
    if (i >= NTOT_C) return;
    int d0 = g_degi[0 * NTOT_C + i];
    int d1 = g_degi[1 * NTOT_C + i];
    int dt = g_degi[2 * NTOT_C + i];
    int dd[5] = {d0 + dt, d1 + dt, d0, d1, dt};
    float w[5];
    #pragma unroll
    for (int s = 0; s < 5; s++) {
        w[s] = (dd[s] > 0) ? rsqrtf((float)dd[s]) : 0.f;
        g_dnv[s * NTOT_C + i] = w[s];
    }
    g_dnv2[0 * NTOT_C + i] = make_float2(w[0], w[2]);  // (c0, a0)
    g_dnv2[1 * NTOT_C + i] = make_float2(w[1], w[3]);  // (c1, a1)
    g_dnv2[2 * NTOT_C + i] = make_float2(w[0], w[1]);  // (c0, c1)
}

__global__ void k_scanA() {
    int g = blockIdx.y;
    const int* deg = g_degi + g * NTOT_C;
    int* out  = g_off   + g * NOFF;
    int* sums = g_bsums + g * SUMS_STRIDE;
    int idx = blockIdx.x * SCAN_B + threadIdx.x;
    int val = (idx < NTOT_C) ? deg[idx] : 0;
    int lane = threadIdx.x & 31, wid = threadIdx.x >> 5;
    int x = val;
    #pragma unroll
    for (int o = 1; o < 32; o <<= 1) {
        int y = __shfl_up_sync(0xffffffffu, x, o);
        if (lane >= o) x += y;
    }
    __shared__ int ws[8], wbase[8];
    if (lane == 31) ws[wid] = x;
    __syncthreads();
    if (threadIdx.x == 0) {
        int s = 0;
        for (int i = 0; i < 8; i++) { wbase[i] = s; s += ws[i]; }
    }
    __syncthreads();
    int incl = x + wbase[wid];
    if (idx < NOFF) out[idx] = incl - val;
    if (threadIdx.x == SCAN_B - 1) sums[blockIdx.x] = incl;
}

__global__ void k_scanB(int nb) {
    int g = blockIdx.x;
    int* sums = g_bsums + g * SUMS_STRIDE;
    __shared__ int sh[SUMS_STRIDE];
    int tid = threadIdx.x;
    int orig = 0;
    if (tid < nb) { orig = sums[tid]; sh[tid] = orig; }
    __syncthreads();
    for (int o = 1; o < nb; o <<= 1) {
        int v = 0;
        if (tid < nb && tid >= o) v = sh[tid - o];
        __syncthreads();
        if (tid < nb && tid >= o) sh[tid] += v;
        __syncthreads();
    }
    if (tid < nb) sums[tid] = sh[tid] - orig;
}

__global__ void k_scanC() {
    int g = blockIdx.y;
    int idx = blockIdx.x * SCAN_B + threadIdx.x;
    if (idx < NOFF)
        g_off[g * NOFF + idx] += g_bsums[g * SUMS_STRIDE + blockIdx.x];
}

__global__ void k_fill3(const int2* __restrict__ aux, const int2* __restrict__ tgt,
                        int Ea, int Et, int nu) {
    int t = blockIdx.x * blockDim.x + threadIdx.x;
    int2 ed; int slot; long long base;
    if (t < 2 * Ea) {
        ed = aux[t];
        slot = (t < Ea) ? 0 : 1;
        base = (t < Ea) ? 0 : 2LL * Ea;
    } else if (t < 2 * Ea + Et) {
        ed = tgt[t - 2 * Ea]; slot = 2; base = 4LL * Ea;
    } else return;
    int* curs = g_curs + slot * NOFF;
    int* csr  = g_csr + base;
    int u = ed.x, v = nu + ed.y;
    csr[atomicAdd(&curs[u], 1)] = v;
    csr[atomicAdd(&curs[v], 1)] = u;
}

// ---------------------------------------------------------------------------
// Propagation — FOUR nodes per warp, float4 columns
// lanes [8q, 8q+8) -> node 4w+q; each lane covers cols 4s..4s+3 (s = lane&7)
// ---------------------------------------------------------------------------
__device__ __forceinline__ void fma4(float4& a, float w, float4 v) {
    a.x = fmaf(w, v.x, a.x);
    a.y = fmaf(w, v.y, a.y);
    a.z = fmaf(w, v.z, a.z);
    a.w = fmaf(w, v.w, a.w);
}

// paired float2 weights -> two outputs; optional accumulate
__global__ void __launch_bounds__(256)
k_dual_w4(const int* __restrict__ csr, const int* __restrict__ off,
          const float* __restrict__ src,
          const float2* __restrict__ w2,
          const float* __restrict__ wXs, const float* __restrict__ wYs,
          float* __restrict__ outX, float* __restrict__ outY, int ntot, int accum) {
    int w = (blockIdx.x * blockDim.x + threadIdx.x) >> 5;
    int lane = threadIdx.x & 31;
    int q   = lane >> 3;
    int sub = lane & 7;
    int u = 4 * w + q;
    int k = 0, end = 0;
    if (u < ntot) { k = off[u]; end = off[u + 1]; }
    float4 aX = make_float4(0.f, 0.f, 0.f, 0.f);
    float4 aY = make_float4(0.f, 0.f, 0.f, 0.f);
    for (; k < end; k += 8) {
        int e[8]; float2 ww[8];
        #pragma unroll
        for (int j = 0; j < 8; j++) {
            int kk = k + j;
            e[j] = __ldg(&csr[kk < end ? kk : k]);
        }
        #pragma unroll
        for (int j = 0; j < 8; j++)
            ww[j] = (k + j < end) ? __ldg(&w2[e[j]]) : make_float2(0.f, 0.f);
        #pragma unroll
        for (int j = 0; j < 8; j++) {
            float4 v = __ldg((const float4*)(src + (size_t)e[j] * D) + sub);
            fma4(aX, ww[j].x, v);
            fma4(aY, ww[j].y, v);
        }
    }
    if (u >= ntot) return;
    size_t o = (size_t)u * D + 4 * sub;
    float sx = __ldg(&wXs[u]);
    float sy = __ldg(&wYs[u]);
    float4 rx = make_float4(sx * aX.x, sx * aX.y, sx * aX.z, sx * aX.w);
    float4 ry = make_float4(sy * aY.x, sy * aY.y, sy * aY.z, sy * aY.w);
    if (accum) {
        float4 px = *(const float4*)(outX + o);
        float4 py = *(const float4*)(outY + o);
        rx.x += px.x; rx.y += px.y; rx.z += px.z; rx.w += px.w;
        ry.x += py.x; ry.y += py.y; ry.z += py.z; ry.w += py.w;
    }
    *(float4*)(outX + o) = rx;
    *(float4*)(outY + o) = ry;
}

// aux layer-2: out = (w[u]*gather + src + base)/3, quad nodes
__global__ void __launch_bounds__(256)
k_gcn_w4(const int* __restrict__ csr, const int* __restrict__ off,
         const float* __restrict__ w,
         const float* __restrict__ src, const float* __restrict__ base,
         float* __restrict__ out, int ntot) {
    int wp = (blockIdx.x * blockDim.x + threadIdx.x) >> 5;
    int lane = threadIdx.x & 31;
    int q   = lane >> 3;
    int sub = lane & 7;
    int u = 4 * wp + q;
    int k = 0, end = 0;
    if (u < ntot) { k = off[u]; end = off[u + 1]; }
    float4 acc = make_float4(0.f, 0.f, 0.f, 0.f);
    for (; k < end; k += 8) {
        int e[8]; float ww[8];
        #pragma unroll
        for (int j = 0; j < 8; j++) {
            int kk = k + j;
            e[j] = __ldg(&csr[kk < end ? kk : k]);
        }
        #pragma unroll
        for (int j = 0; j < 8; j++)
            ww[j] = (k + j < end) ? __ldg(&w[e[j]]) : 0.f;
        #pragma unroll
        for (int j = 0; j < 8; j++) {
            float4 v = __ldg((const float4*)(src + (size_t)e[j] * D) + sub);
            fma4(acc, ww[j], v);
        }
    }
    if (u >= ntot) return;
    size_t o = (size_t)u * D + 4 * sub;
    float wu = __ldg(&w[u]);
    float4 s = *(const float4*)(src + o);
    float4 b = *(const float4*)(base + o);
    float4 r;
    r.x = (wu * acc.x + s.x + b.x) * (1.f / 3.f);
    r.y = (wu * acc.y + s.y + b.y) * (1.f / 3.f);
    r.z = (wu * acc.z + s.z + b.z) * (1.f / 3.f);
    r.w = (wu * acc.w + s.w + b.w) * (1.f / 3.f);
    *(float4*)(out + o) = r;
}

// de layer1: one weight vector, two srcs -> two outputs, quad nodes
__global__ void __launch_bounds__(256)
k_dual_s4(const int* __restrict__ csr, const int* __restrict__ off,
          const float* __restrict__ s0, const float* __restrict__ s1,
          const float* __restrict__ w,
          float* __restrict__ o0, float* __restrict__ o1, int ntot) {
    int wp = (blockIdx.x * blockDim.x + threadIdx.x) >> 5;
    int lane = threadIdx.x & 31;
    int q   = lane >> 3;
    int sub = lane & 7;
    int u = 4 * wp + q;
    int k = 0, end = 0;
    if (u < ntot) { k = off[u]; end = off[u + 1]; }
    float4 a0 = make_float4(0.f, 0.f, 0.f, 0.f);
    float4 a1 = make_float4(0.f, 0.f, 0.f, 0.f);
    for (; k < end; k += 8) {
        int e[8]; float ww[8];
        #pragma unroll
        for (int j = 0; j < 8; j++) {
            int kk = k + j;
            e[j] = __ldg(&csr[kk < end ? kk : k]);
        }
        #pragma unroll
        for (int j = 0; j < 8; j++)
            ww[j] = (k + j < end) ? __ldg(&w[e[j]]) : 0.f;
        #pragma unroll
        for (int j = 0; j < 8; j++) {
            size_t rb = (size_t)e[j] * D;
            float4 v0 = __ldg((const float4*)(s0 + rb) + sub);
            float4 v1 = __ldg((const float4*)(s1 + rb) + sub);
            fma4(a0, ww[j], v0);
            fma4(a1, ww[j], v1);
        }
    }
    if (u >= ntot) return;
    size_t o = (size_t)u * D + 4 * sub;
    float wu = __ldg(&w[u]);
    *(float4*)(o0 + o) = make_float4(wu * a0.x, wu * a0.y, wu * a0.z, wu * a0.w);
    *(float4*)(o1 + o) = make_float4(wu * a1.x, wu * a1.y, wu * a1.z, wu * a1.w);
}

// ---------------------------------------------------------------------------
// Scoring (identical to R10)
// ---------------------------------------------------------------------------
__global__ void k_score_comb(const int* __restrict__ csrA0, const int* __restrict__ offA0,
                             const int* __restrict__ csrA1, const int* __restrict__ offA1,
                             const int* __restrict__ csrT, const int* __restrict__ offT,
                             const float* __restrict__ w0, const float* __restrict__ w1,
                             const float* __restrict__ nxt0, const float* __restrict__ nxt1,
                             const float* __restrict__ base,
                             const int* __restrict__ batch, int B, int nu) {
    int which = blockIdx.y;
    const int* csrA = which ? csrA1 : csrA0;
    const int* offA = which ? offA1 : offA0;
    const float* w   = which ? w1 : w0;
    const float* nxt = which ? nxt1 : nxt0;
    int wp = (blockIdx.x * blockDim.x + threadIdx.x) >> 5;
    if (wp >= B) return;
    int lane = threadIdx.x & 31;
    const int* row = batch + (size_t)wp * 9;
    int nd[3] = {row[0], nu + row[1], nu + row[2]};
    float val[3];
    #pragma unroll
    for (int t = 0; t < 3; t++) {
        int r = nd[t];
        float g = gather_w(csrA, offA[r], offA[r + 1], w, nxt, lane)
                + gather_w(csrT, offT[r], offT[r + 1], w, nxt, lane);
        size_t o = (size_t)r * D + lane;
        val[t] = base[o] + nxt[o] + __ldg(&w[r]) * g;
    }
    float pp = val[0] * val[1], nn = val[0] * val[2];
    #pragma unroll
    for (int o = 16; o; o >>= 1) {
        pp += __shfl_xor_sync(0xffffffffu, pp, o);
        nn += __shfl_xor_sync(0xffffffffu, nn, o);
    }
    if (lane == 0) {
        g_sc[(0 * 2 + which) * BMAX + wp] = fmaxf(pp * (1.f / 9.f), 0.f);
        g_sc[(1 * 2 + which) * BMAX + wp] = fmaxf(nn * (1.f / 9.f), 0.f);
    }
}

__global__ void k_score_de(const int* __restrict__ csrT, const int* __restrict__ offT,
                           const float* __restrict__ wT,
                           const float* __restrict__ d0, const float* __restrict__ d1,
                           const float* __restrict__ ae0, const float* __restrict__ ae1,
                           const int* __restrict__ batch, int B, int nu) {
    int wp = (blockIdx.x * blockDim.x + threadIdx.x) >> 5;
    if (wp >= B) return;
    int lane = threadIdx.x & 31;
    const int* row = batch + (size_t)wp * 9;
    int nd[3] = {row[0], nu + row[1], nu + row[2]};
    float v0[3], v1[3];
    #pragma unroll
    for (int t = 0; t < 3; t++) {
        int r = nd[t];
        int k = offT[r], end = offT[r + 1];
        float a0 = 0.f, a1 = 0.f;
        for (; k + 8 <= end; k += 8) {
            int e[8]; float wj[8];
            #pragma unroll
            for (int j = 0; j < 8; j++) e[j] = __ldg(&csrT[k + j]);
            #pragma unroll
            for (int j = 0; j < 8; j++) wj[j] = __ldg(&wT[e[j]]);
            #pragma unroll
            for (int j = 0; j < 8; j++) {
                size_t ro = (size_t)e[j] * D + lane;
                a0 = fmaf(wj[j], __ldg(&d0[ro]), a0);
                a1 = fmaf(wj[j], __ldg(&d1[ro]), a1);
            }
        }
        for (; k < end; k++) {
            int e = __ldg(&csrT[k]);
            float wj = __ldg(&wT[e]);
            size_t ro = (size_t)e * D + lane;
            a0 = fmaf(wj, __ldg(&d0[ro]), a0);
            a1 = fmaf(wj, __ldg(&d1[ro]), a1);
        }
        size_t o = (size_t)r * D + lane;
        float wr = __ldg(&wT[r]);
        v0[t] = ae0[o] + d0[o] + wr * a0;
        v1[t] = ae1[o] + d1[o] + wr * a1;
    }
    float pp0 = v0[0] * v0[1], nn0 = v0[0] * v0[2];
    float pp1 = v1[0] * v1[1], nn1 = v1[0] * v1[2];
    #pragma unroll
    for (int o = 16; o; o >>= 1) {
        pp0 += __shfl_xor_sync(0xffffffffu, pp0, o);
        nn0 += __shfl_xor_sync(0xffffffffu, nn0, o);
        pp1 += __shfl_xor_sync(0xffffffffu, pp1, o);
        nn1 += __shfl_xor_sync(0xffffffffu, nn1, o);
    }
    if (lane == 0) {
        g_sc[ 8 * BMAX + wp] = fmaxf(pp0 * (1.f / 9.f), 0.f);
        g_sc[10 * BMAX + wp] = fmaxf(nn0 * (1.f / 9.f), 0.f);
        g_sc[ 9 * BMAX + wp] = fmaxf(pp1 * (1.f / 9.f), 0.f);
        g_sc[11 * BMAX + wp] = fmaxf(nn1 * (1.f / 9.f), 0.f);
    }
}

__global__ void k_scores_aux2(const float* __restrict__ ae0, const float* __restrict__ ae1,
                              const int* __restrict__ batch, int B, int nu) {
    __shared__ float sh0[8], sh1[8];
    int warp = (blockIdx.x * blockDim.x + threadIdx.x) >> 5;
    int lane = threadIdx.x & 31;
    int wid  = threadIdx.x >> 5;
    float val0 = 0.f, val1 = 0.f;
    if (warp < B) {
        const int* row = batch + (size_t)warp * 9;
        int u = row[0], p = nu + row[1], n = nu + row[2];
        size_t ou = (size_t)u * D + lane, op = (size_t)p * D + lane, on = (size_t)n * D + lane;
        float e0u = ae0[ou], e1u = ae1[ou];
        float pp0 = e0u * ae0[op], nn0 = e0u * ae0[on];
        float pp1 = e1u * ae1[op], nn1 = e1u * ae1[on];
        const int* r0 = row + 3;
        const int* r1 = row + 6;
        float a0u = ae0[(size_t)r0[0] * D + lane];
        float ps0 = a0u * ae0[(size_t)(nu + r0[1]) * D + lane];
        float ns0 = a0u * ae0[(size_t)(nu + r0[2]) * D + lane];
        float a1u = ae1[(size_t)r1[0] * D + lane];
        float ps1 = a1u * ae1[(size_t)(nu + r1[1]) * D + lane];
        float ns1 = a1u * ae1[(size_t)(nu + r1[2]) * D + lane];
        #pragma unroll
        for (int o = 16; o; o >>= 1) {
            pp0 += __shfl_xor_sync(0xffffffffu, pp0, o);
            nn0 += __shfl_xor_sync(0xffffffffu, nn0, o);
            pp1 += __shfl_xor_sync(0xffffffffu, pp1, o);
            nn1 += __shfl_xor_sync(0xffffffffu, nn1, o);
            ps0 += __shfl_xor_sync(0xffffffffu, ps0, o);
            ns0 += __shfl_xor_sync(0xffffffffu, ns0, o);
            ps1 += __shfl_xor_sync(0xffffffffu, ps1, o);
            ns1 += __shfl_xor_sync(0xffffffffu, ns1, o);
        }
        if (lane == 0) {
            g_sc[4 * BMAX + warp] = fmaxf(pp0, 0.f);
            g_sc[6 * BMAX + warp] = fmaxf(nn0, 0.f);
            g_sc[5 * BMAX + warp] = fmaxf(pp1, 0.f);
            g_sc[7 * BMAX + warp] = fmaxf(nn1, 0.f);
        }
        val0 = logsig(ps0 - ns0);
        val1 = logsig(ps1 - ns1);
    }
    if (lane == 0) { sh0[wid] = val0; sh1[wid] = val1; }
    __syncthreads();
    if (threadIdx.x < 32) {
        float v0 = (threadIdx.x < (blockDim.x >> 5)) ? sh0[threadIdx.x] : 0.f;
        float v1 = (threadIdx.x < (blockDim.x >> 5)) ? sh1[threadIdx.x] : 0.f;
        #pragma unroll
        for (int o = 16; o; o >>= 1) {
            v0 += __shfl_xor_sync(0xffffffffu, v0, o);
            v1 += __shfl_xor_sync(0xffffffffu, v1, o);
        }
        if (threadIdx.x == 0) {
            atomicAdd(&g_scal[0], v0);
            atomicAdd(&g_scal[1], v1);
        }
    }
}

__global__ void k_sumsq2(const float* __restrict__ u, int nuD,
                         const float* __restrict__ it, int niD) {
    __shared__ float sh[8];
    const float* x = blockIdx.y ? it : u;
    int n = blockIdx.y ? niD : nuD;
    int slot = blockIdx.y ? 3 : 2;
    float local = 0.f;
    for (int i = blockIdx.x * blockDim.x + threadIdx.x; i < n; i += gridDim.x * blockDim.x) {
        float v = x[i];
        local += v * v;
    }
    int lane = threadIdx.x & 31, wid = threadIdx.x >> 5;
    #pragma unroll
    for (int o = 16; o; o >>= 1) local += __shfl_xor_sync(0xffffffffu, local, o);
    if (lane == 0) sh[wid] = local;
    __syncthreads();
    if (threadIdx.x < 32) {
        float v = (threadIdx.x < (blockDim.x >> 5)) ? sh[threadIdx.x] : 0.f;
        #pragma unroll
        for (int o = 16; o; o >>= 1) v += __shfl_xor_sync(0xffffffffu, v, o);
        if (threadIdx.x == 0) atomicAdd(&g_scal[slot], v);
    }
}

__global__ void k_final(int B, int ni, float* __restrict__ out) {
    __shared__ float sh[8];
    float local = 0.f;
    for (int b = threadIdx.x; b < B; b += blockDim.x) {
        float cp0 = g_sc[ 0 * BMAX + b], cp1 = g_sc[ 1 * BMAX + b];
        float cn0 = g_sc[ 2 * BMAX + b], cn1 = g_sc[ 3 * BMAX + b];
        float ap0 = g_sc[ 4 * BMAX + b], ap1 = g_sc[ 5 * BMAX + b];
        float an0 = g_sc[ 6 * BMAX + b], an1 = g_sc[ 7 * BMAX + b];
        float dp0 = g_sc[ 8 * BMAX + b], dp1 = g_sc[ 9 * BMAX + b];
        float dn0 = g_sc[10 * BMAX + b], dn1 = g_sc[11 * BMAX + b];
        float ps = (dp0 + dp1) * (cp0 * ap0 + cp1 * ap1);
        float ns = (dn0 + dn1) * (cn0 * an0 + cn1 * an1);
        local += logsig(ps - ns);
    }
    int lane = threadIdx.x & 31, wid = threadIdx.x >> 5;
    #pragma unroll
    for (int o = 16; o; o >>= 1) local += __shfl_xor_sync(0xffffffffu, local, o);
    if (lane == 0) sh[wid] = local;
    __syncthreads();
    if (threadIdx.x == 0) {
        float s = 0.f;
        for (int i = 0; i < (int)(blockDim.x >> 5); i++) s += sh[i];
        float rec  = -s / (float)B;
        float aux  = -(g_scal[0] + g_scal[1]) / (2.f * (float)B);
        float embl = (sqrtf(g_scal[2]) + sqrtf(g_scal[3])) / (float)ni;
        out[0] = rec + 0.5f * aux + 1e-4f * embl;
    }
}

// ---------------------------------------------------------------------------
// Host orchestration (graph-capturable, fork/join dual stream; R10 structure)
// ---------------------------------------------------------------------------
#define TB 256
static inline int nblk(long long n) { return (int)((n + TB - 1) / TB); }

extern "C" void kernel_launch(void* const* d_in, const int* in_sizes, int n_in,
                              void* d_out, int out_size) {
    static cudaStream_t s1 = 0;
    static cudaEvent_t e0 = 0, e1 = 0, e2 = 0, e3 = 0;
    if (!s1) {
        cudaStreamCreateWithFlags(&s1, cudaStreamNonBlocking);
        cudaEventCreateWithFlags(&e0, cudaEventDisableTiming);
        cudaEventCreateWithFlags(&e1, cudaEventDisableTiming);
        cudaEventCreateWithFlags(&e2, cudaEventDisableTiming);
        cudaEventCreateWithFlags(&e3, cudaEventDisableTiming);
    }

    const float* user  = (const float*)d_in[0];
    const float* item  = (const float*)d_in[1];
    const int*   batch = (const int*)  d_in[2];
    const int2*  aux   = (const int2*) d_in[3];
    const int2*  tgt   = (const int2*) d_in[4];

    const int nu   = in_sizes[0] / D;
    const int ni   = in_sizes[1] / D;
    const int ntot = nu + ni;
    const int B    = in_sizes[2] / 9;
    const int Ea   = in_sizes[3] / 4;
    const int Et   = in_sizes[4] / 2;

    float *emb, *pc0, *pc1, *ae0, *ae1, *a0, *a1, *dnv;
    float2* dnv2;
    int *degi, *off, *curs, *csr;
    void* p;
    cudaGetSymbolAddress(&p, g_emb);  emb = (float*)p;
    cudaGetSymbolAddress(&p, g_pc0);  pc0 = (float*)p;
    cudaGetSymbolAddress(&p, g_pc1);  pc1 = (float*)p;
    cudaGetSymbolAddress(&p, g_ae0);  ae0 = (float*)p;
    cudaGetSymbolAddress(&p, g_ae1);  ae1 = (float*)p;
    cudaGetSymbolAddress(&p, g_a0);   a0  = (float*)p;
    cudaGetSymbolAddress(&p, g_a1);   a1  = (float*)p;
    cudaGetSymbolAddress(&p, g_dnv);  dnv = (float*)p;
    cudaGetSymbolAddress(&p, g_dnv2); dnv2 = (float2*)p;
    cudaGetSymbolAddress(&p, g_degi); degi = (int*)p;
    cudaGetSymbolAddress(&p, g_off);  off  = (int*)p;
    cudaGetSymbolAddress(&p, g_curs); curs = (int*)p;
    cudaGetSymbolAddress(&p, g_csr);  csr  = (int*)p;
    void* scalp; cudaGetSymbolAddress(&scalp, g_scal);

    const float* wC0 = dnv + 0 * NTOT_C;
    const float* wC1 = dnv + 1 * NTOT_C;
    const float* wA0 = dnv + 2 * NTOT_C;
    const float* wA1 = dnv + 3 * NTOT_C;
    const float* wT  = dnv + 4 * NTOT_C;

    // ---- init + fork sumsq to side stream ----
    cudaMemsetAsync(scalp, 0, 4 * sizeof(float), 0);
    cudaEventRecord(e0, 0);
    cudaStreamWaitEvent(s1, e0, 0);
    {
        dim3 g(512, 2);
        k_sumsq2<<<g, TB, 0, s1>>>(user, nu * D, item, ni * D);
    }
    cudaMemcpyAsync(emb, user, (size_t)nu * D * sizeof(float), cudaMemcpyDeviceToDevice, 0);
    cudaMemcpyAsync(emb + (size_t)nu * D, item, (size_t)ni * D * sizeof(float),
                    cudaMemcpyDeviceToDevice, 0);

    // ---- build ----
    cudaMemsetAsync(degi, 0, 3 * NTOT_C * sizeof(int), 0);
    k_deg3<<<nblk(2LL * Ea + Et), TB>>>(aux, tgt, Ea, Et, nu);
    k_dinv5<<<nblk(NTOT_C), TB>>>();
    dim3 gScan(NBLK_SCAN, 3);
    k_scanA<<<gScan, SCAN_B>>>();
    k_scanB<<<3, 1024>>>(NBLK_SCAN);
    k_scanC<<<gScan, SCAN_B>>>();
    cudaMemcpyAsync(curs, off, 3 * NOFF * sizeof(int), cudaMemcpyDeviceToDevice, 0);
    k_fill3<<<nblk(2LL * Ea + Et), TB>>>(aux, tgt, Ea, Et, nu);

    const long long bA0 = 0, bA1 = 2LL * Ea, bT = 4LL * Ea;
    const int* offA0 = off + 0 * NOFF;
    const int* offA1 = off + 1 * NOFF;
    const int* offT  = off + 2 * NOFF;
    const int nquad = (ntot + 3) / 4;
    const int gcnB4 = nblk((long long)nquad * 32);
    const int sblk  = nblk((long long)B * 32);

    // ---- layer-1 (quad-node dual-weight; tgt pass accumulates) ----
    k_dual_w4<<<gcnB4, TB>>>(csr + bA0, offA0, emb, dnv2 + 0 * NTOT_C, wC0, wA0,
                             pc0, a0, ntot, 0);
    k_dual_w4<<<gcnB4, TB>>>(csr + bA1, offA1, emb, dnv2 + 1 * NTOT_C, wC1, wA1,
                             pc1, a1, ntot, 0);
    k_dual_w4<<<gcnB4, TB>>>(csr + bT,  offT,  emb, dnv2 + 2 * NTOT_C, wC0, wC1,
                             pc0, pc1, ntot, 1);

    // fork comb scoring to side stream
    cudaEventRecord(e1, 0);
    cudaStreamWaitEvent(s1, e1, 0);
    {
        dim3 g(sblk, 2);
        k_score_comb<<<g, TB, 0, s1>>>(csr + bA0, offA0, csr + bA1, offA1,
                                       csr + bT, offT, wC0, wC1, pc0, pc1, emb,
                                       batch, B, nu);
    }

    // ---- aux layer-2 -> ae (quad nodes) ----
    k_gcn_w4<<<gcnB4, TB>>>(csr + bA0, offA0, wA0, a0, emb, ae0, ntot);
    k_gcn_w4<<<gcnB4, TB>>>(csr + bA1, offA1, wA1, a1, emb, ae1, ntot);

    // fork aux scores to side stream
    cudaEventRecord(e2, 0);
    cudaStreamWaitEvent(s1, e2, 0);
    k_scores_aux2<<<sblk, TB, 0, s1>>>(ae0, ae1, batch, B, nu);

    // ---- de layer-1 (quad nodes, dual source) + de scoring ----
    float* d0 = a0;
    float* d1 = a1;
    k_dual_s4<<<gcnB4, TB>>>(csr + bT, offT, ae0, ae1, wT, d0, d1, ntot);
    k_score_de<<<sblk, TB>>>(csr + bT, offT, wT, d0, d1, ae0, ae1, batch, B, nu);

    // ---- join + finalize ----
    cudaEventRecord(e3, s1);
    cudaStreamWaitEvent(0, e3, 0);
    k_final<<<1, TB>>>(B, ni, (float*)d_out);
}